// round 15
// baseline (speedup 1.0000x reference)
#include <cuda_runtime.h>
#include <math.h>

#define BB 8
#define HH 512
#define WW 512
#define NPIX (BB*HH*WW)

#define NBLK1 (BB*HH)         // 4096 pass1 blocks (one per row)
#define NBLK2 (64*8)          // 512 pass2 blocks (8-row x 512-col bands, 16 px/thread)
#define DSENT 30000

// Packed row-EDT distances, ONE byte per pixel: lo nibble = gt distance,
// hi nibble = seg distance, both saturated at 15. Any pixel whose 2D window
// min could involve a saturated nibble lands in the exact cold tail.
__device__ unsigned char g_pack[NPIX];
// Per-block partial sums (no hot atomics).
__device__ double g_part[NBLK1 * 4];
__device__ double g_hd[NBLK2];
__device__ unsigned g_count;   // zero-init at load; last block resets it

// Nearest-set-bit distance in a 512-bit row stored as 16 uint32 words
// (set bit == background). Returns linear distance, DSENT if none.
__device__ __forceinline__ int nz_d(const unsigned* __restrict__ z, int j) {
    int w  = j >> 5;
    int jb = j & 31;
    int dl = DSENT;
    unsigned t = z[w] & (0xFFFFFFFFu >> (31 - jb));
    if (t) {
        dl = jb - (31 - __clz(t));
    } else {
        #pragma unroll 4
        for (int ww = w - 1; ww >= 0; --ww) {
            unsigned zz = z[ww];
            if (zz) { dl = j - (ww * 32 + 31 - __clz(zz)); break; }
        }
    }
    int dr = DSENT;
    unsigned u = z[w] & (0xFFFFFFFFu << jb);
    if (u) {
        dr = (__ffs(u) - 1) - jb;
    } else {
        #pragma unroll 4
        for (int ww = w + 1; ww < 16; ++ww) {
            unsigned zz = z[ww];
            if (zz) { dr = ww * 32 + (__ffs(zz) - 1) - j; break; }
        }
    }
    return min(dl, dr);
}

// Pack per-thread 4-bit nibbles into 32-bit row-mask words.
__device__ __forceinline__ unsigned pack_nibbles(unsigned nib) {
    unsigned v = nib | (__shfl_xor_sync(0xFFFFFFFFu, nib, 1) << 4);
    v = v | (__shfl_xor_sync(0xFFFFFFFFu, v, 2) << 8);
    v = v | (__shfl_xor_sync(0xFFFFFFFFu, v, 4) << 16);
    return v;   // valid at lanes == 0 (mod 8)
}

// Exact 1D row distance for both masks, scanning raw inputs. Cold path only.
__device__ __noinline__ void rowdist2(const float* __restrict__ outputs,
                                      const int* __restrict__ label,
                                      int b, int row, int j, int& dg, int& ds) {
    size_t base = ((size_t)(b * 2 + 1) * HH + row) * WW;
    dg = DSENT; ds = DSENT;
    for (int d = 0; d < WW; d++) {
        int jl = j - d, jr = j + d;
        if (dg == DSENT) {
            bool hit = (jl >= 0 && label[base + jl] <= 0) ||
                       (jr < WW && label[base + jr] <= 0);
            if (hit) dg = d;
        }
        if (ds == DSENT) {
            bool hit = (jl >= 0 && outputs[base + jl] <= 0.5f) ||
                       (jr < WW && outputs[base + jr] <= 0.5f);
            if (hit) ds = d;
        }
        if (dg != DSENT && ds != DSENT) break;
    }
}

// Exact cold tail: full 2D windowed search from the raw inputs (ignores the
// possibly-saturated nibble estimate entirely). P ~ 2^-27 per pixel.
__device__ __noinline__ void tail_exact(const float* __restrict__ outputs,
                                        const int* __restrict__ label,
                                        int b, int i, int j, int& g, int& s) {
    g = 1 << 30; s = 1 << 30;
    for (int r = 0; r < HH; r++) {
        int r2 = r * r;
        if (r2 >= g && r2 >= s) break;
        int a, c;
        if (i - r >= 0) {
            rowdist2(outputs, label, b, i - r, j, a, c);
            g = min(g, a * a + r2); s = min(s, c * c + r2);
        }
        if (r > 0 && i + r < HH) {
            rowdist2(outputs, label, b, i + r, j, a, c);
            g = min(g, a * a + r2); s = min(s, c * c + r2);
        }
    }
}

// Pass 1: 128 threads per (batch,row), 4 pixels each; nibble-packed store.
__global__ void __launch_bounds__(128) pass1_k(const float* __restrict__ outputs,
                                               const int* __restrict__ label) {
    int row = blockIdx.x;
    int b   = blockIdx.y;
    int t   = threadIdx.x;
    int wid = t >> 5, lid = t & 31;
    int j4  = t * 4;

    __shared__ unsigned zg[16];   // set bit == (lab == 0)
    __shared__ unsigned zs[16];   // set bit == (p1 <= 0.5)

    size_t base1 = ((size_t)(b * 2 + 1) * HH + row) * WW;
    float4 p1v = *(const float4*)(outputs + base1 + j4);
    int4   lbv = *(const int4*)(label + base1 + j4);

    float p1a[4] = {p1v.x, p1v.y, p1v.z, p1v.w};
    int   lba[4] = {lbv.x, lbv.y, lbv.z, lbv.w};

    unsigned nibg = 0, nibs = 0;
    #pragma unroll
    for (int k = 0; k < 4; k++) {
        nibg |= (lba[k] > 0 ? 0u : 1u) << k;       // set bit == background
        nibs |= (p1a[k] > 0.5f ? 0u : 1u) << k;
    }
    unsigned wg = pack_nibbles(nibg);
    unsigned ws = pack_nibbles(nibs);
    if ((lid & 7) == 0) {
        int wslot = wid * 4 + (lid >> 3);
        zg[wslot] = wg;
        zs[wslot] = ws;
    }
    __syncthreads();

    unsigned st = 0;
    #pragma unroll
    for (int k = 0; k < 4; k++) {
        int dg = min(nz_d(zg, j4 + k), 15);
        int ds = min(nz_d(zs, j4 + k), 15);
        st |= (unsigned)(dg | (ds << 4)) << (8 * k);
    }
    *(unsigned*)(g_pack + ((size_t)b * HH + row) * WW + j4) = st;

    // Pointwise CE/Dice terms (fast-math; p0 = 1 - p1)
    float v0 = 0.f, v1 = 0.f, v2 = 0.f, v3 = 0.f;
    #pragma unroll
    for (int k = 0; k < 4; k++) {
        float p1 = p1a[k];
        float p0 = 1.0f - p1;
        float labf = (lba[k] > 0) ? 1.0f : 0.0f;
        float mx   = fmaxf(p0, p1);
        float lse  = mx + __logf(__expf(p0 - mx) + __expf(p1 - mx));
        float picked = (lba[k] > 0) ? p1 : p0;
        v0 += p1 * labf;
        v1 += p1 * p1;
        v2 += labf;
        v3 += lse - picked;
    }

    #pragma unroll
    for (int off = 16; off > 0; off >>= 1) {
        v0 += __shfl_down_sync(0xFFFFFFFFu, v0, off);
        v1 += __shfl_down_sync(0xFFFFFFFFu, v1, off);
        v2 += __shfl_down_sync(0xFFFFFFFFu, v2, off);
        v3 += __shfl_down_sync(0xFFFFFFFFu, v3, off);
    }
    __shared__ float sb[4][4];
    if (lid == 0) { sb[wid][0] = v0; sb[wid][1] = v1; sb[wid][2] = v2; sb[wid][3] = v3; }
    __syncthreads();
    if (t < 4) {
        double s = 0.0;
        #pragma unroll
        for (int w = 0; w < 4; w++) s += (double)sb[w][t];
        g_part[(b * HH + row) * 4 + t] = s;
    }
}

// Pass 2: column EDT, 16 px/thread. One uint4 window load covers 16 px of
// nibble-packed distances: 5 window + 4 p1 loads per 16 px. Saturation-safe
// (see tail_exact). Nibble-plane SIMD mins via __vminu4.
__global__ void __launch_bounds__(256, 8) pass2_k(const float* __restrict__ outputs,
                                                  const int* __restrict__ label,
                                                  float* __restrict__ out) {
    int b   = blockIdx.y;
    int i   = blockIdx.x * 8 + threadIdx.y;   // row
    int j16 = threadIdx.x * 16;               // first of 16 columns

    const unsigned char* __restrict__ Pb = g_pack + (size_t)b * HH * WW;

    // p1 loads issued early to overlap with window loads
    size_t base1 = ((size_t)(b * 2 + 1) * HH + i) * WW + j16;
    float4 pv0 = *(const float4*)(outputs + base1);
    float4 pv1 = *(const float4*)(outputs + base1 + 4);
    float4 pv2 = *(const float4*)(outputs + base1 + 8);
    float4 pv3 = *(const float4*)(outputs + base1 + 12);

    int iu1 = max(i - 1, 0), id1 = min(i + 1, HH - 1);
    int iu2 = max(i - 2, 0), id2 = min(i + 2, HH - 1);

    uint4 c0v = *(const uint4*)(Pb + (size_t)i   * WW + j16);
    uint4 u1v = *(const uint4*)(Pb + (size_t)iu1 * WW + j16);
    uint4 d1v = *(const uint4*)(Pb + (size_t)id1 * WW + j16);
    uint4 u2v = *(const uint4*)(Pb + (size_t)iu2 * WW + j16);
    uint4 d2v = *(const uint4*)(Pb + (size_t)id2 * WW + j16);

    const unsigned* c0w = (const unsigned*)&c0v;
    const unsigned* u1w = (const unsigned*)&u1v;
    const unsigned* d1w = (const unsigned*)&d1v;
    const unsigned* u2w = (const unsigned*)&u2v;
    const unsigned* d2w = (const unsigned*)&d2v;

    float4 pva[4] = {pv0, pv1, pv2, pv3};
    float hd = 0.f;

    #pragma unroll
    for (int w = 0; w < 4; w++) {
        unsigned c0  = c0w[w];
        unsigned c0g = c0 & 0x0F0F0F0Fu;
        unsigned c0s = (c0 >> 4) & 0x0F0F0F0Fu;
        unsigned m1g = __vminu4(u1w[w] & 0x0F0F0F0Fu, d1w[w] & 0x0F0F0F0Fu);
        unsigned m1s = __vminu4((u1w[w] >> 4) & 0x0F0F0F0Fu, (d1w[w] >> 4) & 0x0F0F0F0Fu);
        unsigned m2g = __vminu4(u2w[w] & 0x0F0F0F0Fu, d2w[w] & 0x0F0F0F0Fu);
        unsigned m2s = __vminu4((u2w[w] >> 4) & 0x0F0F0F0Fu, (d2w[w] >> 4) & 0x0F0F0F0Fu);
        float pw[4] = {pva[w].x, pva[w].y, pva[w].z, pva[w].w};
        #pragma unroll
        for (int px = 0; px < 4; px++) {
            int sh = 8 * px;
            int dg = (int)((c0g >> sh) & 0xFu), ds = (int)((c0s >> sh) & 0xFu);
            int g1 = (int)((m1g >> sh) & 0xFu), s1 = (int)((m1s >> sh) & 0xFu);
            int g2 = (int)((m2g >> sh) & 0xFu), s2 = (int)((m2s >> sh) & 0xFu);
            int g = min(dg * dg, min(g1 * g1 + 1, g2 * g2 + 4));
            int s = min(ds * ds, min(s1 * s1 + 1, s2 * s2 + 4));
            if (g > 9 || s > 9)
                tail_exact(outputs, label, b, i, j16 + w * 4 + px, g, s);
            float labf = (dg != 0) ? 1.0f : 0.0f;   // dg>0 <=> lab>0 (sat keeps >0)
            float dlt  = pw[px] - labf;
            hd += (dlt * dlt) * ((float)g + (float)s);
        }
    }

    #pragma unroll
    for (int off = 16; off > 0; off >>= 1)
        hd += __shfl_down_sync(0xFFFFFFFFu, hd, off);

    __shared__ double sbh[8];
    int tid = threadIdx.y * 32 + threadIdx.x;
    int wid = tid >> 5, lid = tid & 31;
    if (lid == 0) sbh[wid] = (double)hd;
    __syncthreads();

    int bid = blockIdx.y * gridDim.x + blockIdx.x;
    if (tid < 8) {
        double s = sbh[tid];
        #pragma unroll
        for (int off = 4; off > 0; off >>= 1)
            s += __shfl_down_sync(0x000000FFu, s, off);
        if (tid == 0) g_hd[bid] = s;
    }

    // ── last-block finalize ──
    __shared__ bool isLast;
    if (tid == 0) {
        __threadfence();
        unsigned cnum = atomicAdd(&g_count, 1u);
        isLast = (cnum == NBLK2 - 1);
    }
    __syncthreads();
    if (!isLast) return;
    __threadfence();

    double s0 = 0.0, s1 = 0.0, s2 = 0.0, s3 = 0.0, sh = 0.0;
    for (int k = tid; k < NBLK1; k += 256) {
        s0 += g_part[k * 4 + 0];
        s1 += g_part[k * 4 + 1];
        s2 += g_part[k * 4 + 2];
        s3 += g_part[k * 4 + 3];
    }
    for (int k = tid; k < NBLK2; k += 256) sh += g_hd[k];

    #pragma unroll
    for (int off = 16; off > 0; off >>= 1) {
        s0 += __shfl_down_sync(0xFFFFFFFFu, s0, off);
        s1 += __shfl_down_sync(0xFFFFFFFFu, s1, off);
        s2 += __shfl_down_sync(0xFFFFFFFFu, s2, off);
        s3 += __shfl_down_sync(0xFFFFFFFFu, s3, off);
        sh += __shfl_down_sync(0xFFFFFFFFu, sh, off);
    }
    __shared__ double fb[8][5];
    if (lid == 0) { fb[wid][0]=s0; fb[wid][1]=s1; fb[wid][2]=s2; fb[wid][3]=s3; fb[wid][4]=sh; }
    __syncthreads();
    if (tid == 0) {
        double a0d=0, a1d=0, a2d=0, a3d=0, ahd=0;
        #pragma unroll
        for (int w = 0; w < 8; w++) {
            a0d += fb[w][0]; a1d += fb[w][1]; a2d += fb[w][2]; a3d += fb[w][3]; ahd += fb[w][4];
        }
        double N    = (double)NPIX;
        double hdm  = ahd / N;
        double dice = 1.0 - (2.0 * a0d + 1e-6) / (a1d + a2d + 1e-6);
        double ce   = a3d / N;
        // LAM = 1.0, ALPHA = 0.5 -> loss = (ce + dice) + 0.5 * hd
        out[0] = (float)((ce + dice) + 0.5 * hdm);
        g_count = 0;   // reset for next graph replay
    }
}

extern "C" void kernel_launch(void* const* d_in, const int* in_sizes, int n_in,
                              void* d_out, int out_size) {
    const float* outputs = (const float*)d_in[0];
    const int*   label   = (const int*)d_in[1];
    float*       out     = (float*)d_out;

    dim3 g1(HH, BB);
    pass1_k<<<g1, 128>>>(outputs, label);

    dim3 b2(32, 8);   // 256 threads: 32 col-threads (16 px each) x 8 rows
    dim3 g2(HH / 8, BB);
    pass2_k<<<g2, b2>>>(outputs, label, out);
}

// round 17
// speedup vs baseline: 2.1370x; 2.1370x over previous
#include <cuda_runtime.h>
#include <math.h>

#define BB 8
#define HH 512
#define WW 512
#define NPIX (BB*HH*WW)
#define INF_F 1.0e12f

#define NBLK1 (BB*HH)         // 4096 pass1 blocks (one per row)
#define NBLK2 (128*8)         // 1024 pass2 blocks (512x4 tiles, 8 px/thread)
#define DSENT 30000

// Packed row-EDT distances, u8 per mask saturated at 255:
// byte0 = gt distance, byte1 = seg distance (2 bytes per pixel).
__device__ unsigned short g_pack[NPIX];
// Per-block partial sums (no hot atomics).
__device__ double g_part[NBLK1 * 4];
__device__ double g_hd[NBLK2];
__device__ unsigned g_count;   // zero-init at load; last block resets it

// Nearest-set-bit distance in a 512-bit row stored as 16 uint32 words
// (set bit == background). Returns linear distance, DSENT if none.
__device__ __forceinline__ int nz_d(const unsigned* __restrict__ z, int j) {
    int w  = j >> 5;
    int jb = j & 31;
    int dl = DSENT;
    unsigned t = z[w] & (0xFFFFFFFFu >> (31 - jb));
    if (t) {
        dl = jb - (31 - __clz(t));
    } else {
        #pragma unroll 4
        for (int ww = w - 1; ww >= 0; --ww) {
            unsigned zz = z[ww];
            if (zz) { dl = j - (ww * 32 + 31 - __clz(zz)); break; }
        }
    }
    int dr = DSENT;
    unsigned u = z[w] & (0xFFFFFFFFu << jb);
    if (u) {
        dr = (__ffs(u) - 1) - jb;
    } else {
        #pragma unroll 4
        for (int ww = w + 1; ww < 16; ++ww) {
            unsigned zz = z[ww];
            if (zz) { dr = ww * 32 + (__ffs(zz) - 1) - j; break; }
        }
    }
    return min(dl, dr);
}

// Pack per-thread 4-bit nibbles into 32-bit row-mask words.
__device__ __forceinline__ unsigned pack_nibbles(unsigned nib) {
    unsigned v = nib | (__shfl_xor_sync(0xFFFFFFFFu, nib, 1) << 4);
    v = v | (__shfl_xor_sync(0xFFFFFFFFu, v, 2) << 8);
    v = v | (__shfl_xor_sync(0xFFFFFFFFu, v, 4) << 16);
    return v;   // valid at lanes == 0 (mod 8)
}

// Pass 1: 128 threads per (batch,row), 4 pixels each. Loads p1 + label only
// (p0 = 1 - p1, softmax rows sum to 1; err ~1e-7 vs 1e-3 budget). Stores
// u8-packed distances (uint2 per thread).
__global__ void __launch_bounds__(128) pass1_k(const float* __restrict__ outputs,
                                               const int* __restrict__ label) {
    int row = blockIdx.x;
    int b   = blockIdx.y;
    int t   = threadIdx.x;
    int wid = t >> 5, lid = t & 31;
    int j4  = t * 4;

    __shared__ unsigned zg[16];   // set bit == (lab == 0)
    __shared__ unsigned zs[16];   // set bit == (p1 <= 0.5)

    size_t base1 = ((size_t)(b * 2 + 1) * HH + row) * WW;
    float4 p1v = *(const float4*)(outputs + base1 + j4);
    int4   lbv = *(const int4*)(label + base1 + j4);

    float p1a[4] = {p1v.x, p1v.y, p1v.z, p1v.w};
    int   lba[4] = {lbv.x, lbv.y, lbv.z, lbv.w};

    unsigned nibg = 0, nibs = 0;
    #pragma unroll
    for (int k = 0; k < 4; k++) {
        nibg |= (lba[k] > 0 ? 0u : 1u) << k;       // set bit == background
        nibs |= (p1a[k] > 0.5f ? 0u : 1u) << k;
    }
    unsigned wg = pack_nibbles(nibg);
    unsigned ws = pack_nibbles(nibs);
    if ((lid & 7) == 0) {
        int wslot = wid * 4 + (lid >> 3);
        zg[wslot] = wg;
        zs[wslot] = ws;
    }
    __syncthreads();

    unsigned pk[4];
    #pragma unroll
    for (int k = 0; k < 4; k++) {
        int dg = min(nz_d(zg, j4 + k), 255);
        int ds = min(nz_d(zs, j4 + k), 255);
        pk[k] = (unsigned)dg | ((unsigned)ds << 8);
    }
    uint2 st;
    st.x = pk[0] | (pk[1] << 16);
    st.y = pk[2] | (pk[3] << 16);
    *(uint2*)(g_pack + ((size_t)b * HH + row) * WW + j4) = st;

    // Pointwise CE/Dice terms (fast-math; p0 = 1 - p1)
    float v0 = 0.f, v1 = 0.f, v2 = 0.f, v3 = 0.f;
    #pragma unroll
    for (int k = 0; k < 4; k++) {
        float p1 = p1a[k];
        float p0 = 1.0f - p1;
        float labf = (lba[k] > 0) ? 1.0f : 0.0f;
        float mx   = fmaxf(p0, p1);
        float lse  = mx + __logf(__expf(p0 - mx) + __expf(p1 - mx));
        float picked = (lba[k] > 0) ? p1 : p0;
        v0 += p1 * labf;
        v1 += p1 * p1;
        v2 += labf;
        v3 += lse - picked;
    }

    #pragma unroll
    for (int off = 16; off > 0; off >>= 1) {
        v0 += __shfl_down_sync(0xFFFFFFFFu, v0, off);
        v1 += __shfl_down_sync(0xFFFFFFFFu, v1, off);
        v2 += __shfl_down_sync(0xFFFFFFFFu, v2, off);
        v3 += __shfl_down_sync(0xFFFFFFFFu, v3, off);
    }
    __shared__ float sb[4][4];
    if (lid == 0) { sb[wid][0] = v0; sb[wid][1] = v1; sb[wid][2] = v2; sb[wid][3] = v3; }
    __syncthreads();
    if (t < 4) {
        double s = 0.0;
        #pragma unroll
        for (int w = 0; w < 4; w++) s += (double)sb[w][t];
        g_part[(b * HH + row) * 4 + t] = s;
    }
}

// Pass 2: column EDT, 8 px/thread. ONE uint4 covers 8 px of packed u8
// distances -> 5 window loads + 2 p1 loads = 7 LDG per 8 px. labf derived
// from dg==0 (no label stream). __vminu4 SIMD min per radius pair.
__global__ void __launch_bounds__(256) pass2_k(const float* __restrict__ outputs,
                                               float* __restrict__ out) {
    int b  = blockIdx.z;
    int i  = blockIdx.y * 4 + threadIdx.y;   // row
    int j8 = threadIdx.x * 8;                // first of 8 columns (64 thr * 8 = 512)

    const unsigned short* __restrict__ Pb = g_pack + (size_t)b * HH * WW;

    // p1 issued early to overlap with window loads
    size_t base1 = ((size_t)(b * 2 + 1) * HH + i) * WW + j8;
    float4 p1lo = *(const float4*)(outputs + base1);
    float4 p1hi = *(const float4*)(outputs + base1 + 4);

    int iu1 = max(i - 1, 0), id1 = min(i + 1, HH - 1);
    int iu2 = max(i - 2, 0), id2 = min(i + 2, HH - 1);

    uint4 c0v = *(const uint4*)(Pb + (size_t)i   * WW + j8);
    uint4 u1v = *(const uint4*)(Pb + (size_t)iu1 * WW + j8);
    uint4 d1v = *(const uint4*)(Pb + (size_t)id1 * WW + j8);
    uint4 u2v = *(const uint4*)(Pb + (size_t)iu2 * WW + j8);
    uint4 d2v = *(const uint4*)(Pb + (size_t)id2 * WW + j8);

    const unsigned* c0w = (const unsigned*)&c0v;
    const unsigned* u1w = (const unsigned*)&u1v;
    const unsigned* d1w = (const unsigned*)&d1v;
    const unsigned* u2w = (const unsigned*)&u2v;
    const unsigned* d2w = (const unsigned*)&d2v;

    int bestG[8], bestS[8];
    unsigned labB[8];
    bool anyTail = false;
    #pragma unroll
    for (int k = 0; k < 4; k++) {
        unsigned m1 = __vminu4(u1w[k], d1w[k]);   // per-byte min, radius 1
        unsigned m2 = __vminu4(u2w[k], d2w[k]);   // per-byte min, radius 2
        // pixel 2k (low half of word)
        {
            int dg = (int)(c0w[k] & 0xFFu), ds = (int)((c0w[k] >> 8) & 0xFFu);
            int g1 = (int)(m1 & 0xFFu), s1 = (int)((m1 >> 8) & 0xFFu);
            int g2 = (int)(m2 & 0xFFu), s2 = (int)((m2 >> 8) & 0xFFu);
            int g = min(dg * dg, min(g1 * g1 + 1, g2 * g2 + 4));
            int s = min(ds * ds, min(s1 * s1 + 1, s2 * s2 + 4));
            bestG[2 * k] = g; bestS[2 * k] = s;
            labB[2 * k] = (unsigned)(dg != 0);
            anyTail |= (g > 9) | (s > 9);
        }
        // pixel 2k+1 (high half of word)
        {
            int dg = (int)((c0w[k] >> 16) & 0xFFu), ds = (int)(c0w[k] >> 24);
            int g1 = (int)((m1 >> 16) & 0xFFu), s1 = (int)(m1 >> 24);
            int g2 = (int)((m2 >> 16) & 0xFFu), s2 = (int)(m2 >> 24);
            int g = min(dg * dg, min(g1 * g1 + 1, g2 * g2 + 4));
            int s = min(ds * ds, min(s1 * s1 + 1, s2 * s2 + 4));
            bestG[2 * k + 1] = g; bestS[2 * k + 1] = s;
            labB[2 * k + 1] = (unsigned)(dg != 0);
            anyTail |= (g > 9) | (s > 9);
        }
    }

    if (anyTail) {
        #pragma unroll
        for (int k = 0; k < 8; k++) {
            if (bestG[k] <= 9 && bestS[k] <= 9) continue;
            int j = j8 + k;
            for (int r = 3; r < HH; r++) {
                int r2 = r * r;
                if (r2 >= bestG[k] && r2 >= bestS[k]) break;
                if (i - r >= 0) {
                    unsigned cc = Pb[(size_t)(i - r) * WW + j];
                    int vg = (int)(cc & 0xFFu);
                    int vs = (int)(cc >> 8);
                    bestG[k] = min(bestG[k], vg * vg + r2);
                    bestS[k] = min(bestS[k], vs * vs + r2);
                }
                if (i + r < HH) {
                    unsigned cc = Pb[(size_t)(i + r) * WW + j];
                    int vg = (int)(cc & 0xFFu);
                    int vs = (int)(cc >> 8);
                    bestG[k] = min(bestG[k], vg * vg + r2);
                    bestS[k] = min(bestS[k], vs * vs + r2);
                }
            }
        }
    }

    float p1a[8] = {p1lo.x, p1lo.y, p1lo.z, p1lo.w, p1hi.x, p1hi.y, p1hi.z, p1hi.w};
    float hd = 0.f;
    #pragma unroll
    for (int k = 0; k < 8; k++) {
        float labf = (float)labB[k];   // dg>0 <=> lab>0
        float dlt  = p1a[k] - labf;
        hd += (dlt * dlt) * ((float)bestS[k] + (float)bestG[k]);
    }

    #pragma unroll
    for (int off = 16; off > 0; off >>= 1)
        hd += __shfl_down_sync(0xFFFFFFFFu, hd, off);

    __shared__ double sbh[8];
    int tid = threadIdx.y * 64 + threadIdx.x;
    int wid = tid >> 5, lid = tid & 31;
    if (lid == 0) sbh[wid] = (double)hd;
    __syncthreads();

    int bid = blockIdx.z * gridDim.y + blockIdx.y;
    if (tid < 8) {
        double s = sbh[tid];
        #pragma unroll
        for (int off = 4; off > 0; off >>= 1)
            s += __shfl_down_sync(0x000000FFu, s, off);
        if (tid == 0) g_hd[bid] = s;
    }

    // ── last-block finalize ──
    __shared__ bool isLast;
    if (tid == 0) {
        __threadfence();
        unsigned cnum = atomicAdd(&g_count, 1u);
        isLast = (cnum == NBLK2 - 1);
    }
    __syncthreads();
    if (!isLast) return;
    __threadfence();

    double s0 = 0.0, s1 = 0.0, s2 = 0.0, s3 = 0.0, sh = 0.0;
    for (int k = tid; k < NBLK1; k += 256) {
        s0 += g_part[k * 4 + 0];
        s1 += g_part[k * 4 + 1];
        s2 += g_part[k * 4 + 2];
        s3 += g_part[k * 4 + 3];
    }
    for (int k = tid; k < NBLK2; k += 256) sh += g_hd[k];

    #pragma unroll
    for (int off = 16; off > 0; off >>= 1) {
        s0 += __shfl_down_sync(0xFFFFFFFFu, s0, off);
        s1 += __shfl_down_sync(0xFFFFFFFFu, s1, off);
        s2 += __shfl_down_sync(0xFFFFFFFFu, s2, off);
        s3 += __shfl_down_sync(0xFFFFFFFFu, s3, off);
        sh += __shfl_down_sync(0xFFFFFFFFu, sh, off);
    }
    __shared__ double fb[8][5];
    if (lid == 0) { fb[wid][0]=s0; fb[wid][1]=s1; fb[wid][2]=s2; fb[wid][3]=s3; fb[wid][4]=sh; }
    __syncthreads();
    if (tid == 0) {
        double a0d=0, a1d=0, a2d=0, a3d=0, ahd=0;
        #pragma unroll
        for (int w = 0; w < 8; w++) {
            a0d += fb[w][0]; a1d += fb[w][1]; a2d += fb[w][2]; a3d += fb[w][3]; ahd += fb[w][4];
        }
        double N    = (double)NPIX;
        double hdm  = ahd / N;
        double dice = 1.0 - (2.0 * a0d + 1e-6) / (a1d + a2d + 1e-6);
        double ce   = a3d / N;
        // LAM = 1.0, ALPHA = 0.5 -> loss = (ce + dice) + 0.5 * hd
        out[0] = (float)((ce + dice) + 0.5 * hdm);
        g_count = 0;   // reset for next graph replay
    }
}

extern "C" void kernel_launch(void* const* d_in, const int* in_sizes, int n_in,
                              void* d_out, int out_size) {
    const float* outputs = (const float*)d_in[0];
    const int*   label   = (const int*)d_in[1];
    float*       out     = (float*)d_out;

    dim3 g1(HH, BB);
    pass1_k<<<g1, 128>>>(outputs, label);

    dim3 b2(64, 4);
    dim3 g2(1, 128, BB);
    pass2_k<<<g2, b2>>>(outputs, out);
}